// round 14
// baseline (speedup 1.0000x reference)
#include <cuda_runtime.h>
#include <cstdint>
#include <math.h>

#define BATCH 2
#define NH    12
#define HD    64
#define DIM   768
#define QT    8
#define QHH   14
#define QW    14
#define SEQ   1568
#define KSEQ  1600
#define MROWS 3136
#define LOG2E 1.44269504f

// ---------------- scratch ------------------------------------------------------
__device__ float g_qh[BATCH*NH*KSEQ*HD];
__device__ float g_kh[BATCH*NH*KSEQ*HD];
__device__ float g_vt[BATCH*NH*HD*KSEQ];
__device__ float g_attn[MROWS*DIM];
__device__ float g_wq[DIM*DIM];
__device__ float g_wk[DIM*DIM];
__device__ float g_wv[DIM*DIM];
__device__ float g_wo[DIM*DIM];
__device__ float g_qr[MROWS*DIM];
__device__ float g_kr[MROWS*DIM];

// ---------------- helpers ------------------------------------------------------
__device__ __forceinline__ uint32_t f2tf32(float x) {
    uint32_t r;
    asm("cvt.rna.tf32.f32 %0, %1;" : "=r"(r) : "f"(x));
    return r;
}
__device__ __forceinline__ float ex2(float x) {
    float r;
    asm("ex2.approx.ftz.f32 %0, %1;" : "=f"(r) : "f"(x));
    return r;
}
__device__ __forceinline__ void mma_tf32(float* c, const uint32_t* a, const uint32_t* b) {
    asm volatile(
        "mma.sync.aligned.m16n8k8.row.col.f32.tf32.tf32.f32 "
        "{%0,%1,%2,%3}, {%4,%5,%6,%7}, {%8,%9}, {%0,%1,%2,%3};"
        : "+f"(c[0]), "+f"(c[1]), "+f"(c[2]), "+f"(c[3])
        : "r"(a[0]), "r"(a[1]), "r"(a[2]), "r"(a[3]), "r"(b[0]), "r"(b[1]));
}
__device__ __forceinline__ uint32_t smem_u32(const void* p) {
    uint32_t a;
    asm("{ .reg .u64 t; cvta.to.shared.u64 t, %1; cvt.u32.u64 %0, t; }" : "=r"(a) : "l"(p));
    return a;
}
#define CP16(dst, src) \
    asm volatile("cp.async.cg.shared.global [%0], [%1], 16;" :: "r"(dst), "l"(src))
#define CP_COMMIT() asm volatile("cp.async.commit_group;" ::: "memory")
#define CP_WAIT0()  asm volatile("cp.async.wait_group 0;" ::: "memory")
#define CP_WAIT1()  asm volatile("cp.async.wait_group 1;" ::: "memory")

__device__ __forceinline__ uint16_t pack_idx(int gk) {
    int gq = gk < SEQ ? gk : SEQ - 1;
    int kt = gq / (QHH * QW);
    int rem = gq - kt * (QHH * QW);
    int khh = rem / QW;
    int kww = rem - khh * QW;
    return (uint16_t)(kt | (khh << 3) | (kww << 7));
}

// ---------------- fused tf32-RNA rounding prepass -----------------------------
#define PRE_BLOCKS (4 * 576 + 2 * 2352)

__global__ __launch_bounds__(256)
void round_all(const float* __restrict__ Wq, const float* __restrict__ Wk,
               const float* __restrict__ Wv, const float* __restrict__ Wo,
               const float* __restrict__ q,  const float* __restrict__ k,
               float* __restrict__ wq, float* __restrict__ wk,
               float* __restrict__ wv, float* __restrict__ wo,
               float* __restrict__ qr, float* __restrict__ kr)
{
    int blk = blockIdx.x;
    const float* src;
    float* dst;
    int base;
    if      (blk < 576)  { src = Wq; dst = wq; base = 0; }
    else if (blk < 1152) { src = Wk; dst = wk; base = 576; }
    else if (blk < 1728) { src = Wv; dst = wv; base = 1152; }
    else if (blk < 2304) { src = Wo; dst = wo; base = 1728; }
    else if (blk < 4656) { src = q;  dst = qr; base = 2304; }
    else                 { src = k;  dst = kr; base = 4656; }
    int i = (blk - base) * 256 + threadIdx.x;
    float4 v = ((const float4*)src)[i];
    uint4 u = make_uint4(f2tf32(v.x), f2tf32(v.y), f2tf32(v.z), f2tf32(v.w));
    ((uint4*)dst)[i] = u;
}

// ---------------- tf32 mma GEMM: 64x128 tiles, cp.async, v2 fragments ---------
#define KC 32
#define LDT 40
#define STAGE_A (64 * LDT)              // 2560 words
#define STAGE_B (128 * LDT)             // 5120 words
#define EPI_PITCH 132
#define GEMM_SMEM (2 * (STAGE_A + STAGE_B) * 4)   // 61440 B

__device__ __forceinline__
void gemm_body(const float* __restrict__ A, const float* __restrict__ W,
               const float* __restrict__ bias, float* __restrict__ dst,
               int headMode)
{
    extern __shared__ float smf[];
    uint32_t* As = (uint32_t*)smf;                  // [2][64*40]
    uint32_t* Bs = As + 2 * STAGE_A;                // [2][128*40]
    const uint32_t smb = smem_u32(smf);
    const uint32_t bsb = smb + 2 * STAGE_A * 4;

    const int tid = threadIdx.x;
    const int lane = tid & 31;
    const int wid = tid >> 5;
    const int wm = wid >> 2;           // 0..1
    const int wn = wid & 3;            // 0..3
    const int rowBlk = blockIdx.y * 64;
    const int colBlk = blockIdx.x * 128;
    const int q4 = lane & 3;
    const int g4 = lane >> 2;

    float acc[2][4][4];
    #pragma unroll
    for (int mi = 0; mi < 2; mi++)
        #pragma unroll
        for (int ni = 0; ni < 4; ni++)
            #pragma unroll
            for (int e = 0; e < 4; e++) acc[mi][ni][e] = 0.f;

    // fill mapping (rows always valid: M = 49*64, N = 6*128)
    const int arow = tid >> 2;                 // 0..63
    const int ac16 = (tid & 3) * 2;            // 2 chunks
    const int brow = tid >> 1;                 // 0..127
    const int bc16 = (tid & 1) * 4;            // 4 chunks
    const float* aptr = A + (size_t)(rowBlk + arow) * DIM;
    const float* wptr = W + (size_t)(colBlk + brow) * DIM;
    const uint32_t aoff = (uint32_t)arow * LDT * 4u;
    const uint32_t boff = (uint32_t)brow * LDT * 4u;

    const int NCH = DIM / KC;                  // 24

    {   // stage 0 fill
        #pragma unroll
        for (int j = 0; j < 2; j++)
            CP16(smb + aoff + (ac16 + j) * 16, aptr + (ac16 + j) * 4);
        #pragma unroll
        for (int j = 0; j < 4; j++)
            CP16(bsb + boff + (bc16 + j) * 16, wptr + (bc16 + j) * 4);
        CP_COMMIT();
    }

    for (int ch = 0; ch < NCH; ch++) {
        if (ch + 1 < NCH) {
            const int k0 = (ch + 1) * KC;
            const uint32_t sA = ((ch + 1) & 1) * STAGE_A * 4;
            const uint32_t sB = ((ch + 1) & 1) * STAGE_B * 4;
            #pragma unroll
            for (int j = 0; j < 2; j++)
                CP16(smb + sA + aoff + (ac16 + j) * 16, aptr + k0 + (ac16 + j) * 4);
            #pragma unroll
            for (int j = 0; j < 4; j++)
                CP16(bsb + sB + boff + (bc16 + j) * 16, wptr + k0 + (bc16 + j) * 4);
            CP_COMMIT();
            CP_WAIT1();
        } else {
            CP_WAIT0();
        }
        __syncthreads();

        const uint32_t* A0 = As + (ch & 1) * STAGE_A;
        const uint32_t* B0 = Bs + (ch & 1) * STAGE_B;
        #pragma unroll
        for (int ks = 0; ks < 4; ks++) {
            const int pc = ks * 8 + 2 * q4;    // relabeled contraction
            uint32_t afr[2][4], bfr[4][2];
            #pragma unroll
            for (int mi = 0; mi < 2; mi++) {
                const int r = wm * 32 + mi * 16 + g4;
                uint2 u0 = *(const uint2*)&A0[r * LDT + pc];
                uint2 u1 = *(const uint2*)&A0[(r + 8) * LDT + pc];
                afr[mi][0] = u0.x; afr[mi][1] = u1.x;
                afr[mi][2] = u0.y; afr[mi][3] = u1.y;
            }
            #pragma unroll
            for (int ni = 0; ni < 4; ni++) {
                const int bn = wn * 32 + ni * 8 + g4;
                uint2 bf = *(const uint2*)&B0[bn * LDT + pc];
                bfr[ni][0] = bf.x; bfr[ni][1] = bf.y;
            }
            #pragma unroll
            for (int mi = 0; mi < 2; mi++)
                #pragma unroll
                for (int ni = 0; ni < 4; ni++)
                    mma_tf32(acc[mi][ni], afr[mi], bfr[ni]);
        }
        __syncthreads();
    }

    float* epi = smf;
    #pragma unroll
    for (int mi = 0; mi < 2; mi++) {
        const int r = wm * 32 + mi * 16 + g4;
        #pragma unroll
        for (int ni = 0; ni < 4; ni++) {
            const int c = wn * 32 + ni * 8 + 2 * q4;
            *(float2*)&epi[r * EPI_PITCH + c]       = make_float2(acc[mi][ni][0], acc[mi][ni][1]);
            *(float2*)&epi[(r + 8) * EPI_PITCH + c] = make_float2(acc[mi][ni][2], acc[mi][ni][3]);
        }
    }
    __syncthreads();

    for (int it = tid; it < 64 * 32; it += 256) {
        const int m2 = it >> 5;
        const int gm = rowBlk + m2;
        const int c4 = (it & 31) * 4;
        const float4 bv = *(const float4*)(bias + colBlk + c4);
        float4 v;
        v.x = epi[m2 * EPI_PITCH + c4 + 0] + bv.x;
        v.y = epi[m2 * EPI_PITCH + c4 + 1] + bv.y;
        v.z = epi[m2 * EPI_PITCH + c4 + 2] + bv.z;
        v.w = epi[m2 * EPI_PITCH + c4 + 3] + bv.w;
        const int o = colBlk + c4;
        if (headMode == 1) {
            int b = gm / SEQ;
            int pos = gm - b * SEQ;
            int n = o >> 6, c = o & 63;
            *(float4*)(dst + (((size_t)(b * NH + n)) * KSEQ + pos) * HD + c) = v;
        } else if (headMode == 2) {
            int b = gm / SEQ;
            int pos = gm - b * SEQ;
            int n = o >> 6, c = o & 63;
            float* base = dst + ((size_t)(b * NH + n) * HD + c) * KSEQ + pos;
            base[0]        = v.x;
            base[KSEQ]     = v.y;
            base[2 * KSEQ] = v.z;
            base[3 * KSEQ] = v.w;
        } else {
            *(float4*)(dst + (size_t)gm * DIM + o) = v;
        }
    }
}

__global__ __launch_bounds__(256)
void gemm_qkv(const float* __restrict__ q, const float* __restrict__ k,
              const float* __restrict__ Wq, const float* __restrict__ bq,
              const float* __restrict__ Wk, const float* __restrict__ bk,
              const float* __restrict__ Wv, const float* __restrict__ bv,
              float* __restrict__ qh, float* __restrict__ kh, float* __restrict__ vt)
{
    const int z = blockIdx.z;
    const float* A    = (z == 0) ? q  : k;
    const float* W    = (z == 0) ? Wq : (z == 1) ? Wk : Wv;
    const float* bias = (z == 0) ? bq : (z == 1) ? bk : bv;
    float* dst        = (z == 0) ? qh : (z == 1) ? kh : vt;
    gemm_body(A, W, bias, dst, (z == 2) ? 2 : 1);
}

__global__ __launch_bounds__(256)
void gemm_o(const float* __restrict__ A, const float* __restrict__ W,
            const float* __restrict__ bias, float* __restrict__ dst)
{
    gemm_body(A, W, bias, dst, 0);
}

// ---------------- split-K flash attention (R13 body, unchanged) ---------------
#define LDQ 68
#define TILE_WORDS (64 * 64)
#define NT (KSEQ / 64)
#define RED_PITCH 68
#define ATTN_SMEM ((4 * TILE_WORDS + 36 * 64) * 4 + 256)   // 75008 B

__global__ __launch_bounds__(256, 2)
void attn_mma(const float* __restrict__ qh, const float* __restrict__ kh,
              const float* __restrict__ vt,
              const float* __restrict__ rpt, const float* __restrict__ rph,
              const float* __restrict__ rpw,
              float* __restrict__ out)
{
    extern __shared__ float sm[];
    uint32_t* Kb = (uint32_t*)sm;
    uint32_t* Vb = Kb + 2 * TILE_WORDS;
    float* bias_sm = (float*)(Vb + 2 * TILE_WORDS);
    uint16_t* idx_sm = (uint16_t*)(bias_sm + 36 * 64);
    float* Qs = sm;
    float* red  = (float*)Kb;
    float* lred = (float*)Vb;

    const int tid = threadIdx.x;
    const int lane = tid & 31;
    const int wid = tid >> 5;
    const int grp = wid >> 2;
    const int lw  = wid & 3;
    const int nbo = grp * 4;
    const int q4 = lane & 3;
    const int r8 = lane >> 2;
    const int qblk = blockIdx.x;
    const int n = blockIdx.y;
    const int b = blockIdx.z;
    const int bn = b * NH + n;
    const int qbase = qblk * 64;
    const int r0 = lw * 16 + r8;

    const float* qbaseP = qh + (size_t)bn * KSEQ * HD;
    const float* kbaseP = kh + (size_t)bn * KSEQ * HD;
    const float* vtbase = vt + (size_t)bn * HD * KSEQ;

    const uint32_t smb = smem_u32(sm);
    const uint32_t kds = smb;
    const uint32_t vds = smb + 2 * TILE_WORDS * 4;

    {
        const int tx = tid & 15;
        const int ty = tid >> 4;
        const int c0 = tx * 4;
        #pragma unroll
        for (int it = 0; it < 4; it++) {
            int lq = ty + 16 * it;
            int gq = qbase + lq;
            float4 v = make_float4(0,0,0,0);
            if (gq < SEQ) v = *(const float4*)(qbaseP + (size_t)gq * HD + c0);
            Qs[(c0+0)*LDQ + lq] = v.x;
            Qs[(c0+1)*LDQ + lq] = v.y;
            Qs[(c0+2)*LDQ + lq] = v.z;
            Qs[(c0+3)*LDQ + lq] = v.w;
        }
    }
    __syncthreads();

    for (int idx = tid; idx < 64 * 36; idx += 256) {
        int lq = idx & 63;
        int j  = idx >> 6;
        int gq = qbase + lq;
        if (gq >= SEQ) gq = SEQ - 1;
        int t = gq / (QHH * QW);
        int rem = gq - t * (QHH * QW);
        int h = rem / QW;
        int w = rem - h * QW;
        const float* r;
        if (j < 8)       r = rpt + (size_t)(t - j + QT - 1) * HD;
        else if (j < 22) r = rph + (size_t)(h - (j - 8) + QHH - 1) * HD;
        else             r = rpw + (size_t)(w - (j - 22) + QW - 1) * HD;
        float acc = 0.f;
        #pragma unroll
        for (int c = 0; c < HD; c++) acc += Qs[c*LDQ + lq] * r[c];
        const int pos = (lq & 48) + ((lq & 7) << 1) + ((lq >> 3) & 1);
        bias_sm[j * 64 + pos] = acc * LOG2E;
    }
    if (tid < 64) idx_sm[tid] = pack_idx(tid);

    const float QSCALE = 0.125f * LOG2E;
    uint32_t qa[8][4];
    #pragma unroll
    for (int ks = 0; ks < 8; ks++) {
        const int pc = ks * 8 + 2 * q4;
        qa[ks][0] = f2tf32(QSCALE * Qs[pc*LDQ + r0]);
        qa[ks][1] = f2tf32(QSCALE * Qs[pc*LDQ + r0 + 8]);
        qa[ks][2] = f2tf32(QSCALE * Qs[(pc+1)*LDQ + r0]);
        qa[ks][3] = f2tf32(QSCALE * Qs[(pc+1)*LDQ + r0 + 8]);
    }
    __syncthreads();

    const int frow  = tid >> 2;
    const int cb16  = (tid & 3) * 4;
    const uint32_t xf = (uint32_t)((frow & 7) << 1);
    const float* krB = kbaseP + (size_t)frow * HD;
    const float* vrB = vtbase + (size_t)frow * KSEQ;

    {
        #pragma unroll
        for (int j = 0; j < 4; j++) {
            const int c16 = cb16 + j;
            const uint32_t pw = (uint32_t)frow * 64u + ((uint32_t)c16 ^ xf) * 4u;
            CP16(kds + pw * 4, krB + c16 * 4);
            CP16(vds + pw * 4, vrB + c16 * 4);
        }
        CP_COMMIT();
    }

    float accO[8][4];
    #pragma unroll
    for (int nb = 0; nb < 8; nb++)
        #pragma unroll
        for (int e = 0; e < 4; e++) accO[nb][e] = 0.f;
    float l0 = 0.f, l1 = 0.f;

    const int posr = (r0 & 48) + ((r0 & 7) << 1);
    const uint32_t xv = (uint32_t)(r8 << 3);

    for (int ti = 0; ti < NT; ti++) {
        CP_WAIT0();
        __syncthreads();

        if (ti + 1 < NT) {
            const int nb4 = ((ti + 1) & 1) * TILE_WORDS * 4;
            const float* kr = krB + (size_t)(ti + 1) * 64 * HD;
            const float* vr = vrB + (ti + 1) * 64;
            #pragma unroll
            for (int j = 0; j < 4; j++) {
                const int c16 = cb16 + j;
                const uint32_t pw = (uint32_t)frow * 64u + ((uint32_t)c16 ^ xf) * 4u;
                CP16(kds + nb4 + pw * 4, kr + c16 * 4);
                CP16(vds + nb4 + pw * 4, vr + c16 * 4);
            }
            CP_COMMIT();
            if (tid < 64) idx_sm[((ti + 1) & 1) * 64 + tid] = pack_idx((ti + 1) * 64 + tid);
        }

        const uint32_t* K0 = Kb + (ti & 1) * TILE_WORDS;
        const uint32_t* V0 = Vb + (ti & 1) * TILE_WORDS;
        const uint16_t* idxc = idx_sm + (ti & 1) * 64;
        const int kb = ti * 64;

        float sc[4][4];
        #pragma unroll
        for (int j = 0; j < 4; j++)
            #pragma unroll
            for (int e = 0; e < 4; e++) sc[j][e] = 0.f;
        #pragma unroll
        for (int ks = 0; ks < 8; ks++) {
            const uint32_t pcx = ((uint32_t)(ks * 8 + 2 * q4)) ^ xv;
            #pragma unroll
            for (int j = 0; j < 4; j++) {
                uint2 bfr = *(const uint2*)&K0[((nbo + j) * 8 + r8) * 64 + pcx];
                mma_tf32(sc[j], qa[ks], (const uint32_t*)&bfr);
            }
        }

        if (ti < NT - 1) {
            #pragma unroll
            for (int j = 0; j < 4; j++) {
                const int col = (nbo + j) * 8 + 2 * q4;
                #pragma unroll
                for (int jj = 0; jj < 2; jj++) {
                    const uint32_t e = idxc[col + jj];
                    float2 bt = *(const float2*)&bias_sm[(e & 7) * 64 + posr];
                    float2 bh = *(const float2*)&bias_sm[(8 + ((e >> 3) & 15)) * 64 + posr];
                    float2 bw = *(const float2*)&bias_sm[(22 + (e >> 7)) * 64 + posr];
                    sc[j][jj]     += bt.x + bh.x + bw.x;
                    sc[j][jj + 2] += bt.y + bh.y + bw.y;
                }
            }
        } else {
            #pragma unroll
            for (int j = 0; j < 4; j++) {
                const int col = (nbo + j) * 8 + 2 * q4;
                #pragma unroll
                for (int jj = 0; jj < 2; jj++) {
                    if (kb + col + jj < SEQ) {
                        const uint32_t e = idxc[col + jj];
                        float2 bt = *(const float2*)&bias_sm[(e & 7) * 64 + posr];
                        float2 bh = *(const float2*)&bias_sm[(8 + ((e >> 3) & 15)) * 64 + posr];
                        float2 bw = *(const float2*)&bias_sm[(22 + (e >> 7)) * 64 + posr];
                        sc[j][jj]     += bt.x + bh.x + bw.x;
                        sc[j][jj + 2] += bt.y + bh.y + bw.y;
                    } else {
                        sc[j][jj] = -1e30f;
                        sc[j][jj + 2] = -1e30f;
                    }
                }
            }
        }

        #pragma unroll
        for (int j = 0; j < 4; j++) {
            sc[j][0] = ex2(sc[j][0]);
            sc[j][1] = ex2(sc[j][1]);
            sc[j][2] = ex2(sc[j][2]);
            sc[j][3] = ex2(sc[j][3]);
            l0 += sc[j][0] + sc[j][1];
            l1 += sc[j][2] + sc[j][3];
        }

        #pragma unroll
        for (int kc = 0; kc < 4; kc++) {
            uint32_t pa[4];
            pa[0] = f2tf32(sc[kc][0]);
            pa[1] = f2tf32(sc[kc][2]);
            pa[2] = f2tf32(sc[kc][1]);
            pa[3] = f2tf32(sc[kc][3]);
            const uint32_t pkx = ((uint32_t)((nbo + kc) * 8 + 2 * q4)) ^ xv;
            #pragma unroll
            for (int nb = 0; nb < 8; nb++) {
                uint2 bfr = *(const uint2*)&V0[(nb * 8 + r8) * 64 + pkx];
                mma_tf32(accO[nb], pa, (const uint32_t*)&bfr);
            }
        }
    }

    l0 += __shfl_xor_sync(0xffffffffu, l0, 1);
    l0 += __shfl_xor_sync(0xffffffffu, l0, 2);
    l1 += __shfl_xor_sync(0xffffffffu, l1, 1);
    l1 += __shfl_xor_sync(0xffffffffu, l1, 2);

    __syncthreads();
    if (grp == 1) {
        #pragma unroll
        for (int nb = 0; nb < 8; nb++) {
            const int c = nb * 8 + 2 * q4;
            *(float2*)&red[r0 * RED_PITCH + c]       = make_float2(accO[nb][0], accO[nb][1]);
            *(float2*)&red[(r0 + 8) * RED_PITCH + c] = make_float2(accO[nb][2], accO[nb][3]);
        }
        if (q4 == 0) { lred[r0] = l0; lred[r0 + 8] = l1; }
    }
    __syncthreads();
    if (grp == 0) {
        l0 += lred[r0];
        l1 += lred[r0 + 8];
        const float inv0 = 1.f / l0;
        const float inv1 = 1.f / l1;
        const int gq0 = qbase + r0;
        const int gq1 = gq0 + 8;
        #pragma unroll
        for (int nb = 0; nb < 8; nb++) {
            const int c = nb * 8 + 2 * q4;
            float2 p0 = *(const float2*)&red[r0 * RED_PITCH + c];
            float2 p1 = *(const float2*)&red[(r0 + 8) * RED_PITCH + c];
            const int col0 = n * HD + c;
            if (gq0 < SEQ) {
                float2 o0 = make_float2(
                    __uint_as_float(f2tf32((accO[nb][0] + p0.x) * inv0)),
                    __uint_as_float(f2tf32((accO[nb][1] + p0.y) * inv0)));
                *(float2*)(out + ((size_t)b * SEQ + gq0) * DIM + col0) = o0;
            }
            if (gq1 < SEQ) {
                float2 o1 = make_float2(
                    __uint_as_float(f2tf32((accO[nb][2] + p1.x) * inv1)),
                    __uint_as_float(f2tf32((accO[nb][3] + p1.y) * inv1)));
                *(float2*)(out + ((size_t)b * SEQ + gq1) * DIM + col0) = o1;
            }
        }
    }
}

// ---------------- launch ------------------------------------------------------
extern "C" void kernel_launch(void* const* d_in, const int* in_sizes, int n_in,
                              void* d_out, int out_size)
{
    (void)in_sizes; (void)n_in; (void)out_size;
    const float* q   = (const float*)d_in[0];
    const float* k   = (const float*)d_in[1];
    const float* Wq  = (const float*)d_in[2];
    const float* bq  = (const float*)d_in[3];
    const float* Wk  = (const float*)d_in[4];
    const float* bk  = (const float*)d_in[5];
    const float* Wv  = (const float*)d_in[6];
    const float* bv  = (const float*)d_in[7];
    const float* Wo  = (const float*)d_in[8];
    const float* bo  = (const float*)d_in[9];
    const float* rpt = (const float*)d_in[10];
    const float* rph = (const float*)d_in[11];
    const float* rpw = (const float*)d_in[12];
    float* out = (float*)d_out;

    float *p_qh, *p_kh, *p_vt, *p_attn;
    float *p_wq, *p_wk, *p_wv, *p_wo, *p_qr, *p_kr;
    cudaGetSymbolAddress((void**)&p_qh,   g_qh);
    cudaGetSymbolAddress((void**)&p_kh,   g_kh);
    cudaGetSymbolAddress((void**)&p_vt,   g_vt);
    cudaGetSymbolAddress((void**)&p_attn, g_attn);
    cudaGetSymbolAddress((void**)&p_wq,   g_wq);
    cudaGetSymbolAddress((void**)&p_wk,   g_wk);
    cudaGetSymbolAddress((void**)&p_wv,   g_wv);
    cudaGetSymbolAddress((void**)&p_wo,   g_wo);
    cudaGetSymbolAddress((void**)&p_qr,   g_qr);
    cudaGetSymbolAddress((void**)&p_kr,   g_kr);

    static int smem_set = 0;
    if (!smem_set) {
        cudaFuncSetAttribute(gemm_qkv,
                             cudaFuncAttributeMaxDynamicSharedMemorySize, GEMM_SMEM);
        cudaFuncSetAttribute(gemm_o,
                             cudaFuncAttributeMaxDynamicSharedMemorySize, GEMM_SMEM);
        cudaFuncSetAttribute(attn_mma,
                             cudaFuncAttributeMaxDynamicSharedMemorySize, ATTN_SMEM);
        smem_set = 1;
    }

    round_all<<<PRE_BLOCKS, 256>>>(Wq, Wk, Wv, Wo, q, k,
                                   p_wq, p_wk, p_wv, p_wo, p_qr, p_kr);

    dim3 qkvGrid(DIM / 128, MROWS / 64, 3);            // 6 x 49 x 3
    gemm_qkv<<<qkvGrid, 256, GEMM_SMEM>>>(p_qr, p_kr, p_wq, bq, p_wk, bk, p_wv, bv,
                                          p_qh, p_kh, p_vt);

    dim3 attnGrid((SEQ + 63) / 64, NH, BATCH);         // 25 x 12 x 2
    attn_mma<<<attnGrid, 256, ATTN_SMEM>>>(p_qh, p_kh, p_vt, rpt, rph, rpw, p_attn);

    dim3 oGrid(DIM / 128, MROWS / 64);                 // 6 x 49
    gemm_o<<<oGrid, 256, GEMM_SMEM>>>(p_attn, p_wo, bo, out);
}

// round 15
// speedup vs baseline: 1.0225x; 1.0225x over previous
#include <cuda_runtime.h>
#include <cstdint>
#include <math.h>

#define BATCH 2
#define NH    12
#define HD    64
#define DIM   768
#define QT    8
#define QHH   14
#define QW    14
#define SEQ   1568
#define KSEQ  1600
#define MROWS 3136
#define LOG2E 1.44269504f

// ---------------- scratch ------------------------------------------------------
__device__ float g_qh[BATCH*NH*KSEQ*HD];
__device__ float g_kh[BATCH*NH*KSEQ*HD];
__device__ float g_vt[BATCH*NH*HD*KSEQ];
__device__ float g_attn[MROWS*DIM];
__device__ float g_wq[DIM*DIM];
__device__ float g_wk[DIM*DIM];
__device__ float g_wv[DIM*DIM];
__device__ float g_wo[DIM*DIM];
__device__ float g_qr[MROWS*DIM];   // also reused as gemm_o partial 0
__device__ float g_kr[MROWS*DIM];   // also reused as gemm_o partial 1

// ---------------- helpers ------------------------------------------------------
__device__ __forceinline__ uint32_t f2tf32(float x) {
    uint32_t r;
    asm("cvt.rna.tf32.f32 %0, %1;" : "=r"(r) : "f"(x));
    return r;
}
__device__ __forceinline__ float ex2(float x) {
    float r;
    asm("ex2.approx.ftz.f32 %0, %1;" : "=f"(r) : "f"(x));
    return r;
}
__device__ __forceinline__ void mma_tf32(float* c, const uint32_t* a, const uint32_t* b) {
    asm volatile(
        "mma.sync.aligned.m16n8k8.row.col.f32.tf32.tf32.f32 "
        "{%0,%1,%2,%3}, {%4,%5,%6,%7}, {%8,%9}, {%0,%1,%2,%3};"
        : "+f"(c[0]), "+f"(c[1]), "+f"(c[2]), "+f"(c[3])
        : "r"(a[0]), "r"(a[1]), "r"(a[2]), "r"(a[3]), "r"(b[0]), "r"(b[1]));
}
__device__ __forceinline__ uint32_t smem_u32(const void* p) {
    uint32_t a;
    asm("{ .reg .u64 t; cvta.to.shared.u64 t, %1; cvt.u32.u64 %0, t; }" : "=r"(a) : "l"(p));
    return a;
}
#define CP16(dst, src) \
    asm volatile("cp.async.cg.shared.global [%0], [%1], 16;" :: "r"(dst), "l"(src))
#define CP_COMMIT() asm volatile("cp.async.commit_group;" ::: "memory")
#define CP_WAIT0()  asm volatile("cp.async.wait_group 0;" ::: "memory")
#define CP_WAIT1()  asm volatile("cp.async.wait_group 1;" ::: "memory")

__device__ __forceinline__ uint16_t pack_idx(int gk) {
    int gq = gk < SEQ ? gk : SEQ - 1;
    int kt = gq / (QHH * QW);
    int rem = gq - kt * (QHH * QW);
    int khh = rem / QW;
    int kww = rem - khh * QW;
    return (uint16_t)(kt | (khh << 3) | (kww << 7));
}

// ---------------- fused tf32-RNA rounding prepass -----------------------------
#define PRE_BLOCKS (4 * 576 + 2 * 2352)

__global__ __launch_bounds__(256)
void round_all(const float* __restrict__ Wq, const float* __restrict__ Wk,
               const float* __restrict__ Wv, const float* __restrict__ Wo,
               const float* __restrict__ q,  const float* __restrict__ k,
               float* __restrict__ wq, float* __restrict__ wk,
               float* __restrict__ wv, float* __restrict__ wo,
               float* __restrict__ qr, float* __restrict__ kr)
{
    int blk = blockIdx.x;
    const float* src;
    float* dst;
    int base;
    if      (blk < 576)  { src = Wq; dst = wq; base = 0; }
    else if (blk < 1152) { src = Wk; dst = wk; base = 576; }
    else if (blk < 1728) { src = Wv; dst = wv; base = 1152; }
    else if (blk < 2304) { src = Wo; dst = wo; base = 1728; }
    else if (blk < 4656) { src = q;  dst = qr; base = 2304; }
    else                 { src = k;  dst = kr; base = 4656; }
    int i = (blk - base) * 256 + threadIdx.x;
    float4 v = ((const float4*)src)[i];
    uint4 u = make_uint4(f2tf32(v.x), f2tf32(v.y), f2tf32(v.z), f2tf32(v.w));
    ((uint4*)dst)[i] = u;
}

// ---------------- tf32 mma GEMM (R13 body + kOff/nch params) ------------------
#define KC 32
#define LDT 40
#define STAGE_W (128 * LDT)
#define EPI_PITCH 132
#define GEMM_SMEM (4 * STAGE_W * 4)     // 81920 B

__device__ __forceinline__
void gemm_body(const float* __restrict__ A, const float* __restrict__ W,
               const float* __restrict__ bias, float* __restrict__ dst,
               int M, int headMode, int kOff, int nch)
{
    extern __shared__ float smf[];
    uint32_t* As = (uint32_t*)smf;
    uint32_t* Bs = As + 2 * STAGE_W;
    const uint32_t smb = smem_u32(smf);

    const int tid = threadIdx.x;
    const int lane = tid & 31;
    const int wid = tid >> 5;
    const int wm = wid >> 2;
    const int wn = wid & 3;
    const int rowBlk = blockIdx.y * 128;
    const int colBlk = blockIdx.x * 128;
    const int q4 = lane & 3;
    const int g4 = lane >> 2;

    float acc[4][4][4];
    #pragma unroll
    for (int mi = 0; mi < 4; mi++)
        #pragma unroll
        for (int ni = 0; ni < 4; ni++)
            #pragma unroll
            for (int e = 0; e < 4; e++) acc[mi][ni][e] = 0.f;

    const int lrow = tid >> 1;
    const int lc0 = (tid & 1) * 16;
    const bool avalid = (rowBlk + lrow) < M;
    const float* aptr = A + (size_t)(rowBlk + lrow) * DIM + kOff + lc0;
    const float* wptr = W + (size_t)(colBlk + lrow) * DIM + kOff + lc0;
    const uint32_t thoff = ((uint32_t)lrow * LDT + (uint32_t)lc0) * 4u;

    {
        #pragma unroll
        for (int j = 0; j < 4; j++) {
            if (avalid) CP16(smb + thoff + j * 16, aptr + j * 4);
            CP16(smb + 2 * STAGE_W * 4 + thoff + j * 16, wptr + j * 4);
        }
        CP_COMMIT();
    }

    for (int ch = 0; ch < nch; ch++) {
        if (ch + 1 < nch) {
            const int k0 = (ch + 1) * KC;
            const uint32_t sb4 = ((ch + 1) & 1) * STAGE_W * 4;
            #pragma unroll
            for (int j = 0; j < 4; j++) {
                if (avalid) CP16(smb + sb4 + thoff + j * 16, aptr + k0 + j * 4);
                CP16(smb + 2 * STAGE_W * 4 + sb4 + thoff + j * 16, wptr + k0 + j * 4);
            }
            CP_COMMIT();
            CP_WAIT1();
        } else {
            CP_WAIT0();
        }
        __syncthreads();

        const uint32_t* A0 = As + (ch & 1) * STAGE_W;
        const uint32_t* B0 = Bs + (ch & 1) * STAGE_W;
        #pragma unroll
        for (int ks = 0; ks < 4; ks++) {
            const int pc = ks * 8 + 2 * q4;
            uint32_t afr[4][4], bfr[4][2];
            #pragma unroll
            for (int mi = 0; mi < 4; mi++) {
                const int r = wm * 64 + mi * 16 + g4;
                uint2 u0 = *(const uint2*)&A0[r * LDT + pc];
                uint2 u1 = *(const uint2*)&A0[(r + 8) * LDT + pc];
                afr[mi][0] = u0.x; afr[mi][1] = u1.x;
                afr[mi][2] = u0.y; afr[mi][3] = u1.y;
            }
            #pragma unroll
            for (int ni = 0; ni < 4; ni++) {
                const int bn = wn * 32 + ni * 8 + g4;
                uint2 bf = *(const uint2*)&B0[bn * LDT + pc];
                bfr[ni][0] = bf.x; bfr[ni][1] = bf.y;
            }
            #pragma unroll
            for (int mi = 0; mi < 4; mi++)
                #pragma unroll
                for (int ni = 0; ni < 4; ni++)
                    mma_tf32(acc[mi][ni], afr[mi], bfr[ni]);
        }
        __syncthreads();
    }

    float* epi = smf;
    #pragma unroll
    for (int mi = 0; mi < 4; mi++) {
        const int r = wm * 64 + mi * 16 + g4;
        #pragma unroll
        for (int ni = 0; ni < 4; ni++) {
            const int c = wn * 32 + ni * 8 + 2 * q4;
            *(float2*)&epi[r * EPI_PITCH + c]       = make_float2(acc[mi][ni][0], acc[mi][ni][1]);
            *(float2*)&epi[(r + 8) * EPI_PITCH + c] = make_float2(acc[mi][ni][2], acc[mi][ni][3]);
        }
    }
    __syncthreads();

    for (int it = tid; it < 128 * 32; it += 256) {
        const int m2 = it >> 5;
        const int gm = rowBlk + m2;
        if (gm >= M) continue;
        const int c4 = (it & 31) * 4;
        float4 v;
        v.x = epi[m2 * EPI_PITCH + c4 + 0];
        v.y = epi[m2 * EPI_PITCH + c4 + 1];
        v.z = epi[m2 * EPI_PITCH + c4 + 2];
        v.w = epi[m2 * EPI_PITCH + c4 + 3];
        const int o = colBlk + c4;
        if (headMode != 3) {
            const float4 bv = *(const float4*)(bias + o);
            v.x += bv.x; v.y += bv.y; v.z += bv.z; v.w += bv.w;
        }
        if (headMode == 1) {
            int b = gm / SEQ;
            int pos = gm - b * SEQ;
            int n = o >> 6, c = o & 63;
            *(float4*)(dst + (((size_t)(b * NH + n)) * KSEQ + pos) * HD + c) = v;
        } else if (headMode == 2) {
            int b = gm / SEQ;
            int pos = gm - b * SEQ;
            int n = o >> 6, c = o & 63;
            float* base = dst + ((size_t)(b * NH + n) * HD + c) * KSEQ + pos;
            base[0]        = v.x;
            base[KSEQ]     = v.y;
            base[2 * KSEQ] = v.z;
            base[3 * KSEQ] = v.w;
        } else {
            *(float4*)(dst + (size_t)gm * DIM + o) = v;
        }
    }
}

__global__ __launch_bounds__(256)
void gemm_qkv(const float* __restrict__ q, const float* __restrict__ k,
              const float* __restrict__ Wq, const float* __restrict__ bq,
              const float* __restrict__ Wk, const float* __restrict__ bk,
              const float* __restrict__ Wv, const float* __restrict__ bv,
              float* __restrict__ qh, float* __restrict__ kh, float* __restrict__ vt)
{
    const int z = blockIdx.z;
    const float* A    = (z == 0) ? q  : k;
    const float* W    = (z == 0) ? Wq : (z == 1) ? Wk : Wv;
    const float* bias = (z == 0) ? bq : (z == 1) ? bk : bv;
    float* dst        = (z == 0) ? qh : (z == 1) ? kh : vt;
    gemm_body(A, W, bias, dst, MROWS, (z == 2) ? 2 : 1, 0, DIM / KC);
}

// gemm_o pass 1: split-K partial GEMMs (grid 6 x 25 x 2)
__global__ __launch_bounds__(256)
void gemm_o_split(const float* __restrict__ A, const float* __restrict__ W,
                  float* __restrict__ p0, float* __restrict__ p1)
{
    const int z = blockIdx.z;
    gemm_body(A, W, nullptr, (z == 0) ? p0 : p1, MROWS, 3, z * (DIM / 2), DIM / (2 * KC));
}

// gemm_o pass 2: merge halves + bias
__global__ __launch_bounds__(256)
void add_halves(const float* __restrict__ p0, const float* __restrict__ p1,
                const float* __restrict__ bias, float* __restrict__ out)
{
    const int i = blockIdx.x * 256 + threadIdx.x;      // float4 index
    float4 a = ((const float4*)p0)[i];
    float4 b = ((const float4*)p1)[i];
    float4 bv = ((const float4*)bias)[i % (DIM / 4)];
    float4 v;
    v.x = a.x + b.x + bv.x;
    v.y = a.y + b.y + bv.y;
    v.z = a.z + b.z + bv.z;
    v.w = a.w + b.w + bv.w;
    ((float4*)out)[i] = v;
}

// ---------------- split-K flash attention (R13 body, unchanged) ---------------
#define LDQ 68
#define TILE_WORDS (64 * 64)
#define NT (KSEQ / 64)
#define RED_PITCH 68
#define ATTN_SMEM ((4 * TILE_WORDS + 36 * 64) * 4 + 256)   // 75008 B

__global__ __launch_bounds__(256, 2)
void attn_mma(const float* __restrict__ qh, const float* __restrict__ kh,
              const float* __restrict__ vt,
              const float* __restrict__ rpt, const float* __restrict__ rph,
              const float* __restrict__ rpw,
              float* __restrict__ out)
{
    extern __shared__ float sm[];
    uint32_t* Kb = (uint32_t*)sm;
    uint32_t* Vb = Kb + 2 * TILE_WORDS;
    float* bias_sm = (float*)(Vb + 2 * TILE_WORDS);
    uint16_t* idx_sm = (uint16_t*)(bias_sm + 36 * 64);
    float* Qs = sm;
    float* red  = (float*)Kb;
    float* lred = (float*)Vb;

    const int tid = threadIdx.x;
    const int lane = tid & 31;
    const int wid = tid >> 5;
    const int grp = wid >> 2;
    const int lw  = wid & 3;
    const int nbo = grp * 4;
    const int q4 = lane & 3;
    const int r8 = lane >> 2;
    const int qblk = blockIdx.x;
    const int n = blockIdx.y;
    const int b = blockIdx.z;
    const int bn = b * NH + n;
    const int qbase = qblk * 64;
    const int r0 = lw * 16 + r8;

    const float* qbaseP = qh + (size_t)bn * KSEQ * HD;
    const float* kbaseP = kh + (size_t)bn * KSEQ * HD;
    const float* vtbase = vt + (size_t)bn * HD * KSEQ;

    const uint32_t smb = smem_u32(sm);
    const uint32_t kds = smb;
    const uint32_t vds = smb + 2 * TILE_WORDS * 4;

    {
        const int tx = tid & 15;
        const int ty = tid >> 4;
        const int c0 = tx * 4;
        #pragma unroll
        for (int it = 0; it < 4; it++) {
            int lq = ty + 16 * it;
            int gq = qbase + lq;
            float4 v = make_float4(0,0,0,0);
            if (gq < SEQ) v = *(const float4*)(qbaseP + (size_t)gq * HD + c0);
            Qs[(c0+0)*LDQ + lq] = v.x;
            Qs[(c0+1)*LDQ + lq] = v.y;
            Qs[(c0+2)*LDQ + lq] = v.z;
            Qs[(c0+3)*LDQ + lq] = v.w;
        }
    }
    __syncthreads();

    for (int idx = tid; idx < 64 * 36; idx += 256) {
        int lq = idx & 63;
        int j  = idx >> 6;
        int gq = qbase + lq;
        if (gq >= SEQ) gq = SEQ - 1;
        int t = gq / (QHH * QW);
        int rem = gq - t * (QHH * QW);
        int h = rem / QW;
        int w = rem - h * QW;
        const float* r;
        if (j < 8)       r = rpt + (size_t)(t - j + QT - 1) * HD;
        else if (j < 22) r = rph + (size_t)(h - (j - 8) + QHH - 1) * HD;
        else             r = rpw + (size_t)(w - (j - 22) + QW - 1) * HD;
        float acc = 0.f;
        #pragma unroll
        for (int c = 0; c < HD; c++) acc += Qs[c*LDQ + lq] * r[c];
        const int pos = (lq & 48) + ((lq & 7) << 1) + ((lq >> 3) & 1);
        bias_sm[j * 64 + pos] = acc * LOG2E;
    }
    if (tid < 64) idx_sm[tid] = pack_idx(tid);

    const float QSCALE = 0.125f * LOG2E;
    uint32_t qa[8][4];
    #pragma unroll
    for (int ks = 0; ks < 8; ks++) {
        const int pc = ks * 8 + 2 * q4;
        qa[ks][0] = f2tf32(QSCALE * Qs[pc*LDQ + r0]);
        qa[ks][1] = f2tf32(QSCALE * Qs[pc*LDQ + r0 + 8]);
        qa[ks][2] = f2tf32(QSCALE * Qs[(pc+1)*LDQ + r0]);
        qa[ks][3] = f2tf32(QSCALE * Qs[(pc+1)*LDQ + r0 + 8]);
    }
    __syncthreads();

    const int frow  = tid >> 2;
    const int cb16  = (tid & 3) * 4;
    const uint32_t xf = (uint32_t)((frow & 7) << 1);
    const float* krB = kbaseP + (size_t)frow * HD;
    const float* vrB = vtbase + (size_t)frow * KSEQ;

    {
        #pragma unroll
        for (int j = 0; j < 4; j++) {
            const int c16 = cb16 + j;
            const uint32_t pw = (uint32_t)frow * 64u + ((uint32_t)c16 ^ xf) * 4u;
            CP16(kds + pw * 4, krB + c16 * 4);
            CP16(vds + pw * 4, vrB + c16 * 4);
        }
        CP_COMMIT();
    }

    float accO[8][4];
    #pragma unroll
    for (int nb = 0; nb < 8; nb++)
        #pragma unroll
        for (int e = 0; e < 4; e++) accO[nb][e] = 0.f;
    float l0 = 0.f, l1 = 0.f;

    const int posr = (r0 & 48) + ((r0 & 7) << 1);
    const uint32_t xv = (uint32_t)(r8 << 3);

    for (int ti = 0; ti < NT; ti++) {
        CP_WAIT0();
        __syncthreads();

        if (ti + 1 < NT) {
            const int nb4 = ((ti + 1) & 1) * TILE_WORDS * 4;
            const float* kr = krB + (size_t)(ti + 1) * 64 * HD;
            const float* vr = vrB + (ti + 1) * 64;
            #pragma unroll
            for (int j = 0; j < 4; j++) {
                const int c16 = cb16 + j;
                const uint32_t pw = (uint32_t)frow * 64u + ((uint32_t)c16 ^ xf) * 4u;
                CP16(kds + nb4 + pw * 4, kr + c16 * 4);
                CP16(vds + nb4 + pw * 4, vr + c16 * 4);
            }
            CP_COMMIT();
            if (tid < 64) idx_sm[((ti + 1) & 1) * 64 + tid] = pack_idx((ti + 1) * 64 + tid);
        }

        const uint32_t* K0 = Kb + (ti & 1) * TILE_WORDS;
        const uint32_t* V0 = Vb + (ti & 1) * TILE_WORDS;
        const uint16_t* idxc = idx_sm + (ti & 1) * 64;
        const int kb = ti * 64;

        float sc[4][4];
        #pragma unroll
        for (int j = 0; j < 4; j++)
            #pragma unroll
            for (int e = 0; e < 4; e++) sc[j][e] = 0.f;
        #pragma unroll
        for (int ks = 0; ks < 8; ks++) {
            const uint32_t pcx = ((uint32_t)(ks * 8 + 2 * q4)) ^ xv;
            #pragma unroll
            for (int j = 0; j < 4; j++) {
                uint2 bfr = *(const uint2*)&K0[((nbo + j) * 8 + r8) * 64 + pcx];
                mma_tf32(sc[j], qa[ks], (const uint32_t*)&bfr);
            }
        }

        if (ti < NT - 1) {
            #pragma unroll
            for (int j = 0; j < 4; j++) {
                const int col = (nbo + j) * 8 + 2 * q4;
                #pragma unroll
                for (int jj = 0; jj < 2; jj++) {
                    const uint32_t e = idxc[col + jj];
                    float2 bt = *(const float2*)&bias_sm[(e & 7) * 64 + posr];
                    float2 bh = *(const float2*)&bias_sm[(8 + ((e >> 3) & 15)) * 64 + posr];
                    float2 bw = *(const float2*)&bias_sm[(22 + (e >> 7)) * 64 + posr];
                    sc[j][jj]     += bt.x + bh.x + bw.x;
                    sc[j][jj + 2] += bt.y + bh.y + bw.y;
                }
            }
        } else {
            #pragma unroll
            for (int j = 0; j < 4; j++) {
                const int col = (nbo + j) * 8 + 2 * q4;
                #pragma unroll
                for (int jj = 0; jj < 2; jj++) {
                    if (kb + col + jj < SEQ) {
                        const uint32_t e = idxc[col + jj];
                        float2 bt = *(const float2*)&bias_sm[(e & 7) * 64 + posr];
                        float2 bh = *(const float2*)&bias_sm[(8 + ((e >> 3) & 15)) * 64 + posr];
                        float2 bw = *(const float2*)&bias_sm[(22 + (e >> 7)) * 64 + posr];
                        sc[j][jj]     += bt.x + bh.x + bw.x;
                        sc[j][jj + 2] += bt.y + bh.y + bw.y;
                    } else {
                        sc[j][jj] = -1e30f;
                        sc[j][jj + 2] = -1e30f;
                    }
                }
            }
        }

        #pragma unroll
        for (int j = 0; j < 4; j++) {
            sc[j][0] = ex2(sc[j][0]);
            sc[j][1] = ex2(sc[j][1]);
            sc[j][2] = ex2(sc[j][2]);
            sc[j][3] = ex2(sc[j][3]);
            l0 += sc[j][0] + sc[j][1];
            l1 += sc[j][2] + sc[j][3];
        }

        #pragma unroll
        for (int kc = 0; kc < 4; kc++) {
            uint32_t pa[4];
            pa[0] = f2tf32(sc[kc][0]);
            pa[1] = f2tf32(sc[kc][2]);
            pa[2] = f2tf32(sc[kc][1]);
            pa[3] = f2tf32(sc[kc][3]);
            const uint32_t pkx = ((uint32_t)((nbo + kc) * 8 + 2 * q4)) ^ xv;
            #pragma unroll
            for (int nb = 0; nb < 8; nb++) {
                uint2 bfr = *(const uint2*)&V0[(nb * 8 + r8) * 64 + pkx];
                mma_tf32(accO[nb], pa, (const uint32_t*)&bfr);
            }
        }
    }

    l0 += __shfl_xor_sync(0xffffffffu, l0, 1);
    l0 += __shfl_xor_sync(0xffffffffu, l0, 2);
    l1 += __shfl_xor_sync(0xffffffffu, l1, 1);
    l1 += __shfl_xor_sync(0xffffffffu, l1, 2);

    __syncthreads();
    if (grp == 1) {
        #pragma unroll
        for (int nb = 0; nb < 8; nb++) {
            const int c = nb * 8 + 2 * q4;
            *(float2*)&red[r0 * RED_PITCH + c]       = make_float2(accO[nb][0], accO[nb][1]);
            *(float2*)&red[(r0 + 8) * RED_PITCH + c] = make_float2(accO[nb][2], accO[nb][3]);
        }
        if (q4 == 0) { lred[r0] = l0; lred[r0 + 8] = l1; }
    }
    __syncthreads();
    if (grp == 0) {
        l0 += lred[r0];
        l1 += lred[r0 + 8];
        const float inv0 = 1.f / l0;
        const float inv1 = 1.f / l1;
        const int gq0 = qbase + r0;
        const int gq1 = gq0 + 8;
        #pragma unroll
        for (int nb = 0; nb < 8; nb++) {
            const int c = nb * 8 + 2 * q4;
            float2 p0 = *(const float2*)&red[r0 * RED_PITCH + c];
            float2 p1 = *(const float2*)&red[(r0 + 8) * RED_PITCH + c];
            const int col0 = n * HD + c;
            if (gq0 < SEQ) {
                float2 o0 = make_float2(
                    __uint_as_float(f2tf32((accO[nb][0] + p0.x) * inv0)),
                    __uint_as_float(f2tf32((accO[nb][1] + p0.y) * inv0)));
                *(float2*)(out + ((size_t)b * SEQ + gq0) * DIM + col0) = o0;
            }
            if (gq1 < SEQ) {
                float2 o1 = make_float2(
                    __uint_as_float(f2tf32((accO[nb][2] + p1.x) * inv1)),
                    __uint_as_float(f2tf32((accO[nb][3] + p1.y) * inv1)));
                *(float2*)(out + ((size_t)b * SEQ + gq1) * DIM + col0) = o1;
            }
        }
    }
}

// ---------------- launch ------------------------------------------------------
extern "C" void kernel_launch(void* const* d_in, const int* in_sizes, int n_in,
                              void* d_out, int out_size)
{
    (void)in_sizes; (void)n_in; (void)out_size;
    const float* q   = (const float*)d_in[0];
    const float* k   = (const float*)d_in[1];
    const float* Wq  = (const float*)d_in[2];
    const float* bq  = (const float*)d_in[3];
    const float* Wk  = (const float*)d_in[4];
    const float* bk  = (const float*)d_in[5];
    const float* Wv  = (const float*)d_in[6];
    const float* bv  = (const float*)d_in[7];
    const float* Wo  = (const float*)d_in[8];
    const float* bo  = (const float*)d_in[9];
    const float* rpt = (const float*)d_in[10];
    const float* rph = (const float*)d_in[11];
    const float* rpw = (const float*)d_in[12];
    float* out = (float*)d_out;

    float *p_qh, *p_kh, *p_vt, *p_attn;
    float *p_wq, *p_wk, *p_wv, *p_wo, *p_qr, *p_kr;
    cudaGetSymbolAddress((void**)&p_qh,   g_qh);
    cudaGetSymbolAddress((void**)&p_kh,   g_kh);
    cudaGetSymbolAddress((void**)&p_vt,   g_vt);
    cudaGetSymbolAddress((void**)&p_attn, g_attn);
    cudaGetSymbolAddress((void**)&p_wq,   g_wq);
    cudaGetSymbolAddress((void**)&p_wk,   g_wk);
    cudaGetSymbolAddress((void**)&p_wv,   g_wv);
    cudaGetSymbolAddress((void**)&p_wo,   g_wo);
    cudaGetSymbolAddress((void**)&p_qr,   g_qr);
    cudaGetSymbolAddress((void**)&p_kr,   g_kr);

    static int smem_set = 0;
    if (!smem_set) {
        cudaFuncSetAttribute(gemm_qkv,
                             cudaFuncAttributeMaxDynamicSharedMemorySize, GEMM_SMEM);
        cudaFuncSetAttribute(gemm_o_split,
                             cudaFuncAttributeMaxDynamicSharedMemorySize, GEMM_SMEM);
        cudaFuncSetAttribute(attn_mma,
                             cudaFuncAttributeMaxDynamicSharedMemorySize, ATTN_SMEM);
        smem_set = 1;
    }

    round_all<<<PRE_BLOCKS, 256>>>(Wq, Wk, Wv, Wo, q, k,
                                   p_wq, p_wk, p_wv, p_wo, p_qr, p_kr);

    dim3 qkvGrid(DIM / 128, (MROWS + 127) / 128, 3);   // 6 x 25 x 3
    gemm_qkv<<<qkvGrid, 256, GEMM_SMEM>>>(p_qr, p_kr, p_wq, bq, p_wk, bk, p_wv, bv,
                                          p_qh, p_kh, p_vt);

    dim3 attnGrid((SEQ + 63) / 64, NH, BATCH);         // 25 x 12 x 2
    attn_mma<<<attnGrid, 256, ATTN_SMEM>>>(p_qh, p_kh, p_vt, rpt, rph, rpw, p_attn);

    // gemm_o: split-K pass 1 (partials into dead qr/kr scratch), pass 2 merge
    dim3 oGrid(DIM / 128, (MROWS + 127) / 128, 2);     // 6 x 25 x 2
    gemm_o_split<<<oGrid, 256, GEMM_SMEM>>>(p_attn, p_wo, p_qr, p_kr);
    add_halves<<<MROWS * DIM / 4 / 256, 256>>>(p_qr, p_kr, bo, out);
}